// round 7
// baseline (speedup 1.0000x reference)
#include <cuda_runtime.h>
#include <cuda_bf16.h>
#include <math.h>
#include <stdint.h>

#define NN     4096
#define INF    512
#define HID    8
#define OUTF   256
#define DEGMAX 128
#define LAMBDA_ 0.7f

// ---------------- scratch (static device globals; no allocation) -------------
__device__ int   g_deg[NN];
__device__ int   g_col[NN * DEGMAX];
__device__ __nv_bfloat16 g_xc[NN * 1536];     // [x_hi | x_lo | x_hi]
__device__ __nv_bfloat16 g_bp[512 * 1536];    // B'[n][k]: n<256 -> Wa col, n>=256 -> Wc col
__device__ float g_z0[NN * 512];              // [u = x@Wa | v = x@Wc]
__device__ float g_y1v[NN * 256];
__device__ float g_y2[NN * 256];
__device__ float g_h[NN * HID];
__device__ float g_dst1[NN];
__device__ float g_p1[NN];
__device__ float g_hp[NN];
__device__ float g_dst2[NN];
__device__ float g_p2[NN];
__device__ float g_mask[NN];
__device__ int   g_need2[NN];
__device__ int   g_list[NN];
__device__ int   g_n0;

__device__ __forceinline__ float elu1(float v) {
    return v > 0.0f ? v : (expf(v) - 1.0f);
}

// ======= merged conversion + fused x@W1 GAT front-end ========================
// blocks [0,2048): x -> split-bf16 [x_hi | x_lo | x_hi]  AND  h=x@W1, dst1
//   (block b covers exactly rows 2b, 2b+1 of x: 256 threads * float4 = 2*512)
// blocks [2048,2560): Wsgc -> B'[n][k] (hi for segs 0/1, lo for seg 2)
__global__ void k_conv(const float* __restrict__ x, const float* __restrict__ Wsgc,
                       const float* __restrict__ W1, const float* __restrict__ a1) {
    int t = threadIdx.x;
    if (blockIdx.x < 2048) {
        int idx = blockIdx.x * 256 + t;
        int m = idx >> 7, c4 = idx & 127;
        float4 v = ((const float4*)x)[idx];
        __nv_bfloat16 h0 = __float2bfloat16(v.x), h1 = __float2bfloat16(v.y);
        __nv_bfloat16 h2 = __float2bfloat16(v.z), h3 = __float2bfloat16(v.w);
        __nv_bfloat16 l0 = __float2bfloat16(v.x - __bfloat162float(h0));
        __nv_bfloat16 l1 = __float2bfloat16(v.y - __bfloat162float(h1));
        __nv_bfloat16 l2 = __float2bfloat16(v.z - __bfloat162float(h2));
        __nv_bfloat16 l3 = __float2bfloat16(v.w - __bfloat162float(h3));
        __nv_bfloat162 hA, hB, lA, lB;
        hA.x = h0; hA.y = h1; hB.x = h2; hB.y = h3;
        lA.x = l0; lA.y = l1; lB.x = l2; lB.y = l3;
        __nv_bfloat162* dst = (__nv_bfloat162*)(g_xc + (size_t)m * 1536 + c4 * 4);
        dst[0] = hA; dst[1] = hB;            // seg 0: hi
        dst[256] = lA; dst[257] = lB;        // seg 1: lo
        dst[512] = hA; dst[513] = hB;        // seg 2: hi

        // ---- fused x@W1 partial (W1 is 16KB, L1-resident) ----
        float acc[HID];
#pragma unroll
        for (int f = 0; f < HID; f++) acc[f] = 0.0f;
        const float4* W14 = (const float4*)W1;
#pragma unroll
        for (int e = 0; e < 4; e++) {
            float xv = (e == 0) ? v.x : (e == 1) ? v.y : (e == 2) ? v.z : v.w;
            float4 w0 = W14[(c4 * 4 + e) * 2];
            float4 w1 = W14[(c4 * 4 + e) * 2 + 1];
            acc[0] += xv * w0.x; acc[1] += xv * w0.y;
            acc[2] += xv * w0.z; acc[3] += xv * w0.w;
            acc[4] += xv * w1.x; acc[5] += xv * w1.y;
            acc[6] += xv * w1.z; acc[7] += xv * w1.w;
        }
#pragma unroll
        for (int f = 0; f < HID; f++)
            for (int o = 16; o; o >>= 1) acc[f] += __shfl_xor_sync(~0u, acc[f], o);
        __shared__ float part[8][HID];
        __shared__ float hrow[2][HID];
        int w = t >> 5, lane = t & 31;
        if (lane == 0) {
#pragma unroll
            for (int f = 0; f < HID; f++) part[w][f] = acc[f];
        }
        __syncthreads();
        if (t < 16) {    // warps 0-3 -> local row 0, warps 4-7 -> local row 1
            int lr = t >> 3, f = t & 7;
            float s = part[lr * 4 + 0][f] + part[lr * 4 + 1][f] +
                      part[lr * 4 + 2][f] + part[lr * 4 + 3][f];
            g_h[(blockIdx.x * 2 + lr) * HID + f] = s;
            hrow[lr][f] = s * a1[HID + f];
        }
        __syncthreads();
        if (t < 2) {
            float d = 0.0f;
#pragma unroll
            for (int f = 0; f < HID; f++) d += hrow[t][f];
            g_dst1[blockIdx.x * 2 + t] = d;
        }
    } else {
        int n = blockIdx.x - 2048;
#pragma unroll
        for (int i = 0; i < 6; i++) {
            int k = t + i * 256;                          // 1536 k's
            int kk = k & 511, seg = k >> 9;
            float wf = (n < 256) ? Wsgc[(size_t)kk * OUTF + n]
                                 : Wsgc[(size_t)(1024 + kk) * OUTF + (n - 256)];
            __nv_bfloat16 h = __float2bfloat16(wf);
            __nv_bfloat16 o = (seg == 2) ? __float2bfloat16(wf - __bfloat162float(h)) : h;
            g_bp[(size_t)n * 1536 + k] = o;
        }
    }
}

// =================== mma.sync GEMM: Z0 = Xc @ Bp^T ===========================
#define GBM 128
#define GBN 128

__device__ __forceinline__ uint32_t smem_u32(const void* p) {
    uint32_t a;
    asm("{ .reg .u64 t; cvta.to.shared.u64 t, %1; cvt.u32.u64 %0, t; }"
        : "=r"(a) : "l"(p));
    return a;
}
__device__ __forceinline__ void ldmx4(uint32_t* r, uint32_t addr) {
    asm volatile("ldmatrix.sync.aligned.m8n8.x4.shared.b16 {%0,%1,%2,%3}, [%4];"
                 : "=r"(r[0]), "=r"(r[1]), "=r"(r[2]), "=r"(r[3]) : "r"(addr));
}
__device__ __forceinline__ void mma16816(float* d, const uint32_t* a, const uint32_t* b) {
    asm volatile(
        "mma.sync.aligned.m16n8k16.row.col.f32.bf16.bf16.f32 "
        "{%0,%1,%2,%3}, {%4,%5,%6,%7}, {%8,%9}, {%0,%1,%2,%3};"
        : "+f"(d[0]), "+f"(d[1]), "+f"(d[2]), "+f"(d[3])
        : "r"(a[0]), "r"(a[1]), "r"(a[2]), "r"(a[3]), "r"(b[0]), "r"(b[1]));
}

__global__ void __launch_bounds__(256, 1) k_gemm() {
    __shared__ uint4 As[2][GBM * 4];
    __shared__ uint4 Bs[2][GBN * 4];

    int t = threadIdx.x, wid = t >> 5, lane = t & 31;
    int bm = blockIdx.x * GBM, bn = blockIdx.y * GBN;
    int wm = (wid >> 2) * 64;
    int wn = (wid & 3) * 32;

    const __nv_bfloat16* Ag = g_xc + (size_t)bm * 1536;
    const __nv_bfloat16* Bg = g_bp + (size_t)bn * 1536;

    int la_m[2], la_c[2];
#pragma unroll
    for (int q = 0; q < 2; q++) {
        int idx = t + q * 256;
        la_m[q] = idx >> 2;
        la_c[q] = idx & 3;
    }

    float acc[4][4][4];
#pragma unroll
    for (int i = 0; i < 4; i++)
#pragma unroll
        for (int j = 0; j < 4; j++)
#pragma unroll
            for (int r = 0; r < 4; r++) acc[i][j][r] = 0.0f;

    int a_r = lane & 15, a_cc = lane >> 4;
    int b_r = (lane & 7) + ((lane >> 4) & 1) * 8, b_cc = (lane >> 3) & 1;

    uint4 ra[2], rb[2];
#pragma unroll
    for (int q = 0; q < 2; q++) {
        ra[q] = *(const uint4*)(Ag + (size_t)la_m[q] * 1536 + la_c[q] * 8);
        rb[q] = *(const uint4*)(Bg + (size_t)la_m[q] * 1536 + la_c[q] * 8);
    }
#pragma unroll
    for (int q = 0; q < 2; q++) {
        int m = la_m[q], c = la_c[q];
        int sw = c ^ ((m >> 1) & 3);
        As[0][m * 4 + sw] = ra[q];
        Bs[0][m * 4 + sw] = rb[q];
    }
    __syncthreads();

    for (int kc = 0; kc < 48; kc++) {
        int cur = kc & 1;
        if (kc < 47) {
#pragma unroll
            for (int q = 0; q < 2; q++) {
                size_t o = (size_t)la_m[q] * 1536 + (kc + 1) * 32 + la_c[q] * 8;
                ra[q] = *(const uint4*)(Ag + o);
                rb[q] = *(const uint4*)(Bg + o);
            }
        }
        uint32_t as_base = smem_u32(&As[cur][0]);
        uint32_t bs_base = smem_u32(&Bs[cur][0]);
#pragma unroll
        for (int kk = 0; kk < 2; kk++) {
            int c0 = kk * 2;
            uint32_t afr[4][4], bfr[2][4];
#pragma unroll
            for (int mi = 0; mi < 4; mi++) {
                int m = wm + mi * 16 + a_r;
                int c = (c0 + a_cc) ^ ((m >> 1) & 3);
                ldmx4(afr[mi], as_base + m * 64 + c * 16);
            }
#pragma unroll
            for (int nj = 0; nj < 2; nj++) {
                int n = wn + nj * 16 + b_r;
                int c = (c0 + b_cc) ^ ((n >> 1) & 3);
                ldmx4(bfr[nj], bs_base + n * 64 + c * 16);
            }
#pragma unroll
            for (int mi = 0; mi < 4; mi++) {
#pragma unroll
                for (int nj = 0; nj < 4; nj++) {
                    mma16816(acc[mi][nj], afr[mi], &bfr[nj >> 1][(nj & 1) * 2]);
                }
            }
        }
        if (kc < 47) {
#pragma unroll
            for (int q = 0; q < 2; q++) {
                int m = la_m[q], c = la_c[q];
                int sw = c ^ ((m >> 1) & 3);
                As[cur ^ 1][m * 4 + sw] = ra[q];
                Bs[cur ^ 1][m * 4 + sw] = rb[q];
            }
            __syncthreads();
        }
    }

#pragma unroll
    for (int mi = 0; mi < 4; mi++) {
        int r0 = bm + wm + mi * 16 + (lane >> 2);
#pragma unroll
        for (int nj = 0; nj < 4; nj++) {
            int c = bn + wn + nj * 8 + (lane & 3) * 2;
            *(float2*)(g_z0 + (size_t)r0 * 512 + c) =
                make_float2(acc[mi][nj][0], acc[mi][nj][1]);
            *(float2*)(g_z0 + (size_t)(r0 + 8) * 512 + c) =
                make_float2(acc[mi][nj][2], acc[mi][nj][3]);
        }
    }
}

// =================== one-pass padded CSR (float4 loads) + init ===============
__global__ void k_csr(const float* __restrict__ adj) {
    if (threadIdx.x < 8) g_need2[blockIdx.x * 8 + threadIdx.x] = 0;
    if (blockIdx.x == 0 && threadIdx.x == 0) g_n0 = 0;

    int row = blockIdx.x * 8 + (threadIdx.x >> 5);
    int lane = threadIdx.x & 31;
    const float4* a = (const float4*)(adj + (size_t)row * NN);
    int base = row * DEGMAX, cnt = 0;
    unsigned below = (1u << lane) - 1u;
#pragma unroll 2
    for (int j0 = 0; j0 < 1024; j0 += 32) {       // 1024 float4 per row
        float4 v = a[j0 + lane];
        unsigned b0 = __ballot_sync(~0u, v.x > 0.5f);
        unsigned b1 = __ballot_sync(~0u, v.y > 0.5f);
        unsigned b2 = __ballot_sync(~0u, v.z > 0.5f);
        unsigned b3 = __ballot_sync(~0u, v.w > 0.5f);
        int p = base + cnt +
                __popc(b0 & below) + __popc(b1 & below) +
                __popc(b2 & below) + __popc(b3 & below);
        int col0 = (j0 + lane) * 4;
        if (v.x > 0.5f) g_col[p++] = col0 + 0;
        if (v.y > 0.5f) g_col[p++] = col0 + 1;
        if (v.z > 0.5f) g_col[p++] = col0 + 2;
        if (v.w > 0.5f) g_col[p++] = col0 + 3;
        cnt += __popc(b0) + __popc(b1) + __popc(b2) + __popc(b3);
    }
    if (lane == 0) g_deg[row] = cnt;
}

// ---------------- global softmax (max-free: |dst| << 80, exp safe) -----------
__global__ void k_softmax(int which) {
    const float* d = which ? g_dst2 : g_dst1;
    float* p = which ? g_p2 : g_p1;
    __shared__ float red[32];
    __shared__ float sh_s;
    int t = threadIdx.x, lane = t & 31, w = t >> 5;
    float s = 0.0f;
    float e0 = expf(d[t]),        e1 = expf(d[t + 1024]);
    float e2 = expf(d[t + 2048]), e3 = expf(d[t + 3072]);
    p[t] = e0; p[t + 1024] = e1; p[t + 2048] = e2; p[t + 3072] = e3;
    s = e0 + e1 + e2 + e3;
    for (int o = 16; o; o >>= 1) s += __shfl_xor_sync(~0u, s, o);
    if (lane == 0) red[w] = s;
    __syncthreads();
    if (t == 0) {
        float ss = 0.0f;
        for (int i = 0; i < 32; i++) ss += red[i];
        sh_s = ss;
    }
    __syncthreads();
    float inv = 1.0f / sh_s;
    p[t] *= inv; p[t + 1024] *= inv; p[t + 2048] *= inv; p[t + 3072] *= inv;
}

// ------- sparse GAT agg layer 1 (8-wide) + fused h1@W2 epilogue --------------
__global__ void k_agg1(const float* __restrict__ W2, const float* __restrict__ a2) {
    int row = blockIdx.x * 8 + (threadIdx.x >> 5);
    int lane = threadIdx.x & 31;
    int s = row * DEGMAX, deg = g_deg[row];
    float acc[HID];
#pragma unroll
    for (int f = 0; f < HID; f++) acc[f] = 0.0f;
    for (int k = lane; k < deg; k += 32) {
        int j = g_col[s + k];
        float pj = g_p1[j];
        const float* hj = g_h + j * HID;
#pragma unroll
        for (int f = 0; f < HID; f++) acc[f] += pj * hj[f];
    }
#pragma unroll
    for (int f = 0; f < HID; f++)
        for (int o = 16; o; o >>= 1) acc[f] += __shfl_xor_sync(~0u, acc[f], o);
    if (lane == 0) {
        float hp = 0.0f;
#pragma unroll
        for (int f = 0; f < HID; f++) hp += elu1(acc[f]) * W2[f];
        g_hp[row] = hp;
        g_dst2[row] = hp * a2[1];
    }
}

// ------- sparse GAT agg layer 2 (scalar) + mask + fused hop-2/3 flags --------
__global__ void k_agg2() {
    int row = blockIdx.x * 8 + (threadIdx.x >> 5);
    int lane = threadIdx.x & 31;
    int s = row * DEGMAX, deg = g_deg[row];
    float acc = 0.0f;
    for (int k = lane; k < deg; k += 32) {
        int j = g_col[s + k];
        acc += g_p2[j] * g_hp[j];
    }
    for (int o = 16; o; o >>= 1) acc += __shfl_xor_sync(~0u, acc, o);
    float mask = 0.0f;
    if (lane == 0) {
        float sc = elu1(acc);
        mask = sc > LAMBDA_ ? 1.0f : 0.0f;
        g_mask[row] = mask;
        if (mask == 0.0f) {
            int slot = atomicAdd(&g_n0, 1);
            g_list[slot] = row;
        }
    }
    mask = __shfl_sync(~0u, mask, 0);
    if (mask == 0.0f) {
        for (int k = lane; k < deg; k += 32) g_need2[g_col[s + k]] = 1;
    }
}

// =================== SpMMs ====================================================
// hop1: y1v = A@v (always); mask=1 rows also emit out = A@u + bias directly
__global__ void k_spmm1(const float* __restrict__ bsgc, float* __restrict__ out) {
    int row = blockIdx.x;
    int t = threadIdx.x;               // 128: t<64 -> v cols, t>=64 -> u cols
    bool isU = t >= 64;
    if (isU && g_mask[row] == 0.0f) return;
    int cofs = isU ? (t - 64) : (64 + t);
    int s = row * DEGMAX, deg = g_deg[row];
    const float4* X = (const float4*)g_z0;
    float4 acc = make_float4(0.f, 0.f, 0.f, 0.f);
    int k = 0;
    for (; k + 3 < deg; k += 4) {
        int j0 = g_col[s + k], j1 = g_col[s + k + 1];
        int j2 = g_col[s + k + 2], j3 = g_col[s + k + 3];
        float4 v0 = X[(size_t)j0 * 128 + cofs];
        float4 v1 = X[(size_t)j1 * 128 + cofs];
        float4 v2 = X[(size_t)j2 * 128 + cofs];
        float4 v3 = X[(size_t)j3 * 128 + cofs];
        acc.x += v0.x + v1.x + v2.x + v3.x;
        acc.y += v0.y + v1.y + v2.y + v3.y;
        acc.z += v0.z + v1.z + v2.z + v3.z;
        acc.w += v0.w + v1.w + v2.w + v3.w;
    }
    for (; k < deg; k++) {
        int j = g_col[s + k];
        float4 v = X[(size_t)j * 128 + cofs];
        acc.x += v.x; acc.y += v.y; acc.z += v.z; acc.w += v.w;
    }
    if (isU) {
        int c = t - 64;
        float4 b = ((const float4*)bsgc)[c];
        acc.x += b.x; acc.y += b.y; acc.z += b.z; acc.w += b.w;
        ((float4*)out)[(size_t)row * 64 + c] = acc;
    } else {
        ((float4*)g_y1v)[(size_t)row * 64 + t] = acc;
    }
}

// hop2: y2 = A@y1v, only rows that neighbor a masked-0 row
__global__ void k_spmm2() {
    int row = blockIdx.x;
    if (!g_need2[row]) return;
    int t = threadIdx.x;               // 64
    int s = row * DEGMAX, deg = g_deg[row];
    const float4* X = (const float4*)g_y1v;
    float4 acc = make_float4(0.f, 0.f, 0.f, 0.f);
    int k = 0;
    for (; k + 3 < deg; k += 4) {
        int j0 = g_col[s + k], j1 = g_col[s + k + 1];
        int j2 = g_col[s + k + 2], j3 = g_col[s + k + 3];
        float4 v0 = X[(size_t)j0 * 64 + t];
        float4 v1 = X[(size_t)j1 * 64 + t];
        float4 v2 = X[(size_t)j2 * 64 + t];
        float4 v3 = X[(size_t)j3 * 64 + t];
        acc.x += v0.x + v1.x + v2.x + v3.x;
        acc.y += v0.y + v1.y + v2.y + v3.y;
        acc.z += v0.z + v1.z + v2.z + v3.z;
        acc.w += v0.w + v1.w + v2.w + v3.w;
    }
    for (; k < deg; k++) {
        int j = g_col[s + k];
        float4 v = X[(size_t)j * 64 + t];
        acc.x += v.x; acc.y += v.y; acc.z += v.z; acc.w += v.w;
    }
    ((float4*)g_y2)[(size_t)row * 64 + t] = acc;
}

// hop3: out = A@y2 + bias, only masked-0 rows (compacted list)
__global__ void k_spmm3(const float* __restrict__ bsgc, float* __restrict__ out) {
    int b = blockIdx.x;
    if (b >= g_n0) return;
    int row = g_list[b];
    int t = threadIdx.x;               // 64
    int s = row * DEGMAX, deg = g_deg[row];
    const float4* X = (const float4*)g_y2;
    float4 acc = make_float4(0.f, 0.f, 0.f, 0.f);
    int k = 0;
    for (; k + 3 < deg; k += 4) {
        int j0 = g_col[s + k], j1 = g_col[s + k + 1];
        int j2 = g_col[s + k + 2], j3 = g_col[s + k + 3];
        float4 v0 = X[(size_t)j0 * 64 + t];
        float4 v1 = X[(size_t)j1 * 64 + t];
        float4 v2 = X[(size_t)j2 * 64 + t];
        float4 v3 = X[(size_t)j3 * 64 + t];
        acc.x += v0.x + v1.x + v2.x + v3.x;
        acc.y += v0.y + v1.y + v2.y + v3.y;
        acc.z += v0.z + v1.z + v2.z + v3.z;
        acc.w += v0.w + v1.w + v2.w + v3.w;
    }
    for (; k < deg; k++) {
        int j = g_col[s + k];
        float4 v = X[(size_t)j * 64 + t];
        acc.x += v.x; acc.y += v.y; acc.z += v.z; acc.w += v.w;
    }
    float4 bb = ((const float4*)bsgc)[t];
    acc.x += bb.x; acc.y += bb.y; acc.z += bb.z; acc.w += bb.w;
    ((float4*)out)[(size_t)row * 64 + t] = acc;
}

// =================== launch ==================================================
extern "C" void kernel_launch(void* const* d_in, const int* in_sizes, int n_in,
                              void* d_out, int out_size) {
    const float* x    = (const float*)d_in[0];
    const float* adj  = (const float*)d_in[1];
    const float* W1   = (const float*)d_in[2];
    const float* a1   = (const float*)d_in[3];
    const float* W2   = (const float*)d_in[4];
    const float* a2   = (const float*)d_in[5];
    const float* Wsgc = (const float*)d_in[6];
    const float* bsgc = (const float*)d_in[7];
    float* out = (float*)d_out;

    // conversions + fused x@W1 front-end, then tensor GEMM: Z0 = x @ [Wa | Wc]
    k_conv<<<2560, 256>>>(x, Wsgc, W1, a1);
    k_gemm<<<dim3(32, 4), 256>>>();

    // one-pass padded CSR (float4) + filter-state init
    k_csr<<<512, 256>>>(adj);

    // GAT chain (softmax cancellation) -> row mask (+fused flags)
    k_softmax<<<1, 1024>>>(0);
    k_agg1<<<512, 256>>>(W2, a2);
    k_softmax<<<1, 1024>>>(1);
    k_agg2<<<512, 256>>>();

    // hop aggregations (adj^2 output term provably zero); out written in-place
    k_spmm1<<<NN, 128>>>(bsgc, out);
    k_spmm2<<<NN, 64>>>();
    k_spmm3<<<NN, 64>>>(bsgc, out);
}

// round 8
// speedup vs baseline: 1.1918x; 1.1918x over previous
#include <cuda_runtime.h>
#include <cuda_bf16.h>
#include <math.h>
#include <stdint.h>

#define NN     4096
#define INF    512
#define HID    8
#define OUTF   256
#define DEGMAX 128
#define LAMBDA_ 0.7f

// ---------------- scratch (static device globals; no allocation) -------------
__device__ int   g_deg[NN];
__device__ int   g_col[NN * DEGMAX];
__device__ __nv_bfloat16 g_xc[NN * 1536];     // [x_hi | x_lo | x_hi]
__device__ __nv_bfloat16 g_bp[512 * 1536];    // B'[n][k]
__device__ float g_z0[NN * 512];              // [u = x@Wa | v = x@Wc]
__device__ float g_y1v[NN * 256];
__device__ float g_y2[NN * 256];
__device__ float g_h[NN * HID];
__device__ float g_e1[NN];                    // exp(dst1)
__device__ float g_hp[NN];
__device__ float g_e2[NN];                    // exp(dst2)
__device__ float g_mask[NN];
__device__ int   g_need2[NN];
__device__ int   g_list[NN];
__device__ int   g_n0;

__device__ __forceinline__ float elu1(float v) {
    return v > 0.0f ? v : (expf(v) - 1.0f);
}

// ======= merged conversion + fused x@W1 GAT front-end ========================
__global__ void k_conv(const float* __restrict__ x, const float* __restrict__ Wsgc,
                       const float* __restrict__ W1, const float* __restrict__ a1) {
    int t = threadIdx.x;
    if (blockIdx.x < 2048) {
        int idx = blockIdx.x * 256 + t;
        int m = idx >> 7, c4 = idx & 127;
        float4 v = ((const float4*)x)[idx];
        __nv_bfloat16 h0 = __float2bfloat16(v.x), h1 = __float2bfloat16(v.y);
        __nv_bfloat16 h2 = __float2bfloat16(v.z), h3 = __float2bfloat16(v.w);
        __nv_bfloat16 l0 = __float2bfloat16(v.x - __bfloat162float(h0));
        __nv_bfloat16 l1 = __float2bfloat16(v.y - __bfloat162float(h1));
        __nv_bfloat16 l2 = __float2bfloat16(v.z - __bfloat162float(h2));
        __nv_bfloat16 l3 = __float2bfloat16(v.w - __bfloat162float(h3));
        __nv_bfloat162 hA, hB, lA, lB;
        hA.x = h0; hA.y = h1; hB.x = h2; hB.y = h3;
        lA.x = l0; lA.y = l1; lB.x = l2; lB.y = l3;
        __nv_bfloat162* dst = (__nv_bfloat162*)(g_xc + (size_t)m * 1536 + c4 * 4);
        dst[0] = hA; dst[1] = hB;            // seg 0: hi
        dst[256] = lA; dst[257] = lB;        // seg 1: lo
        dst[512] = hA; dst[513] = hB;        // seg 2: hi

        // ---- fused x@W1 partial (W1 is 16KB, L1-resident) ----
        float acc[HID];
#pragma unroll
        for (int f = 0; f < HID; f++) acc[f] = 0.0f;
        const float4* W14 = (const float4*)W1;
#pragma unroll
        for (int e = 0; e < 4; e++) {
            float xv = (e == 0) ? v.x : (e == 1) ? v.y : (e == 2) ? v.z : v.w;
            float4 w0 = W14[(c4 * 4 + e) * 2];
            float4 w1 = W14[(c4 * 4 + e) * 2 + 1];
            acc[0] += xv * w0.x; acc[1] += xv * w0.y;
            acc[2] += xv * w0.z; acc[3] += xv * w0.w;
            acc[4] += xv * w1.x; acc[5] += xv * w1.y;
            acc[6] += xv * w1.z; acc[7] += xv * w1.w;
        }
#pragma unroll
        for (int f = 0; f < HID; f++)
            for (int o = 16; o; o >>= 1) acc[f] += __shfl_xor_sync(~0u, acc[f], o);
        __shared__ float part[8][HID];
        __shared__ float hrow[2][HID];
        int w = t >> 5, lane = t & 31;
        if (lane == 0) {
#pragma unroll
            for (int f = 0; f < HID; f++) part[w][f] = acc[f];
        }
        __syncthreads();
        if (t < 16) {    // warps 0-3 -> local row 0, warps 4-7 -> local row 1
            int lr = t >> 3, f = t & 7;
            float s = part[lr * 4 + 0][f] + part[lr * 4 + 1][f] +
                      part[lr * 4 + 2][f] + part[lr * 4 + 3][f];
            g_h[(blockIdx.x * 2 + lr) * HID + f] = s;
            hrow[lr][f] = s * a1[HID + f];
        }
        __syncthreads();
        if (t < 2) {
            float d = 0.0f;
#pragma unroll
            for (int f = 0; f < HID; f++) d += hrow[t][f];
            g_e1[blockIdx.x * 2 + t] = expf(d);    // producer-side exp
        }
    } else {
        int n = blockIdx.x - 2048;
#pragma unroll
        for (int i = 0; i < 6; i++) {
            int k = t + i * 256;
            int kk = k & 511, seg = k >> 9;
            float wf = (n < 256) ? Wsgc[(size_t)kk * OUTF + n]
                                 : Wsgc[(size_t)(1024 + kk) * OUTF + (n - 256)];
            __nv_bfloat16 h = __float2bfloat16(wf);
            __nv_bfloat16 o = (seg == 2) ? __float2bfloat16(wf - __bfloat162float(h)) : h;
            g_bp[(size_t)n * 1536 + k] = o;
        }
    }
}

// =================== mma.sync GEMM: Z0 = Xc @ Bp^T ===========================
#define GBM 128
#define GBN 128

__device__ __forceinline__ uint32_t smem_u32(const void* p) {
    uint32_t a;
    asm("{ .reg .u64 t; cvta.to.shared.u64 t, %1; cvt.u32.u64 %0, t; }"
        : "=r"(a) : "l"(p));
    return a;
}
__device__ __forceinline__ void ldmx4(uint32_t* r, uint32_t addr) {
    asm volatile("ldmatrix.sync.aligned.m8n8.x4.shared.b16 {%0,%1,%2,%3}, [%4];"
                 : "=r"(r[0]), "=r"(r[1]), "=r"(r[2]), "=r"(r[3]) : "r"(addr));
}
__device__ __forceinline__ void mma16816(float* d, const uint32_t* a, const uint32_t* b) {
    asm volatile(
        "mma.sync.aligned.m16n8k16.row.col.f32.bf16.bf16.f32 "
        "{%0,%1,%2,%3}, {%4,%5,%6,%7}, {%8,%9}, {%0,%1,%2,%3};"
        : "+f"(d[0]), "+f"(d[1]), "+f"(d[2]), "+f"(d[3])
        : "r"(a[0]), "r"(a[1]), "r"(a[2]), "r"(a[3]), "r"(b[0]), "r"(b[1]));
}

__global__ void __launch_bounds__(256, 1) k_gemm() {
    __shared__ uint4 As[2][GBM * 4];
    __shared__ uint4 Bs[2][GBN * 4];

    int t = threadIdx.x, wid = t >> 5, lane = t & 31;
    int bm = blockIdx.x * GBM, bn = blockIdx.y * GBN;
    int wm = (wid >> 2) * 64;
    int wn = (wid & 3) * 32;

    const __nv_bfloat16* Ag = g_xc + (size_t)bm * 1536;
    const __nv_bfloat16* Bg = g_bp + (size_t)bn * 1536;

    int la_m[2], la_c[2];
#pragma unroll
    for (int q = 0; q < 2; q++) {
        int idx = t + q * 256;
        la_m[q] = idx >> 2;
        la_c[q] = idx & 3;
    }

    float acc[4][4][4];
#pragma unroll
    for (int i = 0; i < 4; i++)
#pragma unroll
        for (int j = 0; j < 4; j++)
#pragma unroll
            for (int r = 0; r < 4; r++) acc[i][j][r] = 0.0f;

    int a_r = lane & 15, a_cc = lane >> 4;
    int b_r = (lane & 7) + ((lane >> 4) & 1) * 8, b_cc = (lane >> 3) & 1;

    uint4 ra[2], rb[2];
#pragma unroll
    for (int q = 0; q < 2; q++) {
        ra[q] = *(const uint4*)(Ag + (size_t)la_m[q] * 1536 + la_c[q] * 8);
        rb[q] = *(const uint4*)(Bg + (size_t)la_m[q] * 1536 + la_c[q] * 8);
    }
#pragma unroll
    for (int q = 0; q < 2; q++) {
        int m = la_m[q], c = la_c[q];
        int sw = c ^ ((m >> 1) & 3);
        As[0][m * 4 + sw] = ra[q];
        Bs[0][m * 4 + sw] = rb[q];
    }
    __syncthreads();

    for (int kc = 0; kc < 48; kc++) {
        int cur = kc & 1;
        if (kc < 47) {
#pragma unroll
            for (int q = 0; q < 2; q++) {
                size_t o = (size_t)la_m[q] * 1536 + (kc + 1) * 32 + la_c[q] * 8;
                ra[q] = *(const uint4*)(Ag + o);
                rb[q] = *(const uint4*)(Bg + o);
            }
        }
        uint32_t as_base = smem_u32(&As[cur][0]);
        uint32_t bs_base = smem_u32(&Bs[cur][0]);
#pragma unroll
        for (int kk = 0; kk < 2; kk++) {
            int c0 = kk * 2;
            uint32_t afr[4][4], bfr[2][4];
#pragma unroll
            for (int mi = 0; mi < 4; mi++) {
                int m = wm + mi * 16 + a_r;
                int c = (c0 + a_cc) ^ ((m >> 1) & 3);
                ldmx4(afr[mi], as_base + m * 64 + c * 16);
            }
#pragma unroll
            for (int nj = 0; nj < 2; nj++) {
                int n = wn + nj * 16 + b_r;
                int c = (c0 + b_cc) ^ ((n >> 1) & 3);
                ldmx4(bfr[nj], bs_base + n * 64 + c * 16);
            }
#pragma unroll
            for (int mi = 0; mi < 4; mi++) {
#pragma unroll
                for (int nj = 0; nj < 4; nj++) {
                    mma16816(acc[mi][nj], afr[mi], &bfr[nj >> 1][(nj & 1) * 2]);
                }
            }
        }
        if (kc < 47) {
#pragma unroll
            for (int q = 0; q < 2; q++) {
                int m = la_m[q], c = la_c[q];
                int sw = c ^ ((m >> 1) & 3);
                As[cur ^ 1][m * 4 + sw] = ra[q];
                Bs[cur ^ 1][m * 4 + sw] = rb[q];
            }
            __syncthreads();
        }
    }

#pragma unroll
    for (int mi = 0; mi < 4; mi++) {
        int r0 = bm + wm + mi * 16 + (lane >> 2);
#pragma unroll
        for (int nj = 0; nj < 4; nj++) {
            int c = bn + wn + nj * 8 + (lane & 3) * 2;
            *(float2*)(g_z0 + (size_t)r0 * 512 + c) =
                make_float2(acc[mi][nj][0], acc[mi][nj][1]);
            *(float2*)(g_z0 + (size_t)(r0 + 8) * 512 + c) =
                make_float2(acc[mi][nj][2], acc[mi][nj][3]);
        }
    }
}

// =================== one-pass padded CSR (float4 loads) + init ===============
__global__ void k_csr(const float* __restrict__ adj) {
    if (threadIdx.x < 8) g_need2[blockIdx.x * 8 + threadIdx.x] = 0;
    if (blockIdx.x == 0 && threadIdx.x == 0) g_n0 = 0;

    int row = blockIdx.x * 8 + (threadIdx.x >> 5);
    int lane = threadIdx.x & 31;
    const float4* a = (const float4*)(adj + (size_t)row * NN);
    int base = row * DEGMAX, cnt = 0;
    unsigned below = (1u << lane) - 1u;
#pragma unroll 2
    for (int j0 = 0; j0 < 1024; j0 += 32) {
        float4 v = a[j0 + lane];
        unsigned b0 = __ballot_sync(~0u, v.x > 0.5f);
        unsigned b1 = __ballot_sync(~0u, v.y > 0.5f);
        unsigned b2 = __ballot_sync(~0u, v.z > 0.5f);
        unsigned b3 = __ballot_sync(~0u, v.w > 0.5f);
        int p = base + cnt +
                __popc(b0 & below) + __popc(b1 & below) +
                __popc(b2 & below) + __popc(b3 & below);
        int col0 = (j0 + lane) * 4;
        if (v.x > 0.5f) g_col[p++] = col0 + 0;
        if (v.y > 0.5f) g_col[p++] = col0 + 1;
        if (v.z > 0.5f) g_col[p++] = col0 + 2;
        if (v.w > 0.5f) g_col[p++] = col0 + 3;
        cnt += __popc(b0) + __popc(b1) + __popc(b2) + __popc(b3);
    }
    if (lane == 0) g_deg[row] = cnt;
}

// ---- block-level sum of a 4096-float array (deterministic) ------------------
__device__ __forceinline__ float block_sum_4096(const float* arr, float* red) {
    int t = threadIdx.x, lane = t & 31, w = t >> 5;
    const float4* A4 = (const float4*)arr;
    float s = 0.0f;
#pragma unroll
    for (int q = 0; q < 4; q++) {
        float4 v = A4[t + q * 256];
        s += (v.x + v.y) + (v.z + v.w);
    }
    for (int o = 16; o; o >>= 1) s += __shfl_xor_sync(~0u, s, o);
    if (lane == 0) red[w] = s;
    __syncthreads();
    float S = ((red[0] + red[1]) + (red[2] + red[3])) +
              ((red[4] + red[5]) + (red[6] + red[7]));
    return S;
}

// ------- GAT agg layer 1 (+inline softmax-sum, fused h1@W2, e2 producer) -----
__global__ void k_agg1(const float* __restrict__ W2, const float* __restrict__ a2) {
    __shared__ float red[8];
    float S1 = block_sum_4096(g_e1, red);
    float inv = 1.0f / S1;

    int row = blockIdx.x * 8 + (threadIdx.x >> 5);
    int lane = threadIdx.x & 31;
    int s = row * DEGMAX, deg = g_deg[row];
    float acc[HID];
#pragma unroll
    for (int f = 0; f < HID; f++) acc[f] = 0.0f;
    for (int k = lane; k < deg; k += 32) {
        int j = g_col[s + k];
        float pj = g_e1[j];
        const float* hj = g_h + j * HID;
#pragma unroll
        for (int f = 0; f < HID; f++) acc[f] += pj * hj[f];
    }
#pragma unroll
    for (int f = 0; f < HID; f++)
        for (int o = 16; o; o >>= 1) acc[f] += __shfl_xor_sync(~0u, acc[f], o);
    if (lane == 0) {
        float hp = 0.0f;
#pragma unroll
        for (int f = 0; f < HID; f++) hp += elu1(acc[f] * inv) * W2[f];
        g_hp[row] = hp;
        g_e2[row] = expf(hp * a2[1]);
    }
}

// ------- GAT agg layer 2 (+inline sum) + mask + fused hop-2/3 flags ----------
__global__ void k_agg2() {
    __shared__ float red[8];
    float S2 = block_sum_4096(g_e2, red);
    float inv = 1.0f / S2;

    int row = blockIdx.x * 8 + (threadIdx.x >> 5);
    int lane = threadIdx.x & 31;
    int s = row * DEGMAX, deg = g_deg[row];
    float acc = 0.0f;
    for (int k = lane; k < deg; k += 32) {
        int j = g_col[s + k];
        acc += g_e2[j] * g_hp[j];
    }
    for (int o = 16; o; o >>= 1) acc += __shfl_xor_sync(~0u, acc, o);
    float mask = 0.0f;
    if (lane == 0) {
        float sc = elu1(acc * inv);
        mask = sc > LAMBDA_ ? 1.0f : 0.0f;
        g_mask[row] = mask;
        if (mask == 0.0f) {
            int slot = atomicAdd(&g_n0, 1);
            g_list[slot] = row;
        }
    }
    mask = __shfl_sync(~0u, mask, 0);
    if (mask == 0.0f) {
        for (int k = lane; k < deg; k += 32) g_need2[g_col[s + k]] = 1;
    }
}

// =================== SpMMs ====================================================
__global__ void k_spmm1(const float* __restrict__ bsgc, float* __restrict__ out) {
    int row = blockIdx.x;
    int t = threadIdx.x;               // 128: t<64 -> v cols, t>=64 -> u cols
    bool isU = t >= 64;
    if (isU && g_mask[row] == 0.0f) return;
    int cofs = isU ? (t - 64) : (64 + t);
    int s = row * DEGMAX, deg = g_deg[row];
    const float4* X = (const float4*)g_z0;
    float4 acc = make_float4(0.f, 0.f, 0.f, 0.f);
    int k = 0;
    for (; k + 3 < deg; k += 4) {
        int j0 = g_col[s + k], j1 = g_col[s + k + 1];
        int j2 = g_col[s + k + 2], j3 = g_col[s + k + 3];
        float4 v0 = X[(size_t)j0 * 128 + cofs];
        float4 v1 = X[(size_t)j1 * 128 + cofs];
        float4 v2 = X[(size_t)j2 * 128 + cofs];
        float4 v3 = X[(size_t)j3 * 128 + cofs];
        acc.x += v0.x + v1.x + v2.x + v3.x;
        acc.y += v0.y + v1.y + v2.y + v3.y;
        acc.z += v0.z + v1.z + v2.z + v3.z;
        acc.w += v0.w + v1.w + v2.w + v3.w;
    }
    for (; k < deg; k++) {
        int j = g_col[s + k];
        float4 v = X[(size_t)j * 128 + cofs];
        acc.x += v.x; acc.y += v.y; acc.z += v.z; acc.w += v.w;
    }
    if (isU) {
        int c = t - 64;
        float4 b = ((const float4*)bsgc)[c];
        acc.x += b.x; acc.y += b.y; acc.z += b.z; acc.w += b.w;
        ((float4*)out)[(size_t)row * 64 + c] = acc;
    } else {
        ((float4*)g_y1v)[(size_t)row * 64 + t] = acc;
    }
}

__global__ void k_spmm2() {
    int row = blockIdx.x;
    if (!g_need2[row]) return;
    int t = threadIdx.x;               // 64
    int s = row * DEGMAX, deg = g_deg[row];
    const float4* X = (const float4*)g_y1v;
    float4 acc = make_float4(0.f, 0.f, 0.f, 0.f);
    int k = 0;
    for (; k + 3 < deg; k += 4) {
        int j0 = g_col[s + k], j1 = g_col[s + k + 1];
        int j2 = g_col[s + k + 2], j3 = g_col[s + k + 3];
        float4 v0 = X[(size_t)j0 * 64 + t];
        float4 v1 = X[(size_t)j1 * 64 + t];
        float4 v2 = X[(size_t)j2 * 64 + t];
        float4 v3 = X[(size_t)j3 * 64 + t];
        acc.x += v0.x + v1.x + v2.x + v3.x;
        acc.y += v0.y + v1.y + v2.y + v3.y;
        acc.z += v0.z + v1.z + v2.z + v3.z;
        acc.w += v0.w + v1.w + v2.w + v3.w;
    }
    for (; k < deg; k++) {
        int j = g_col[s + k];
        float4 v = X[(size_t)j * 64 + t];
        acc.x += v.x; acc.y += v.y; acc.z += v.z; acc.w += v.w;
    }
    ((float4*)g_y2)[(size_t)row * 64 + t] = acc;
}

__global__ void k_spmm3(const float* __restrict__ bsgc, float* __restrict__ out) {
    int b = blockIdx.x;
    if (b >= g_n0) return;
    int row = g_list[b];
    int t = threadIdx.x;               // 64
    int s = row * DEGMAX, deg = g_deg[row];
    const float4* X = (const float4*)g_y2;
    float4 acc = make_float4(0.f, 0.f, 0.f, 0.f);
    int k = 0;
    for (; k + 3 < deg; k += 4) {
        int j0 = g_col[s + k], j1 = g_col[s + k + 1];
        int j2 = g_col[s + k + 2], j3 = g_col[s + k + 3];
        float4 v0 = X[(size_t)j0 * 64 + t];
        float4 v1 = X[(size_t)j1 * 64 + t];
        float4 v2 = X[(size_t)j2 * 64 + t];
        float4 v3 = X[(size_t)j3 * 64 + t];
        acc.x += v0.x + v1.x + v2.x + v3.x;
        acc.y += v0.y + v1.y + v2.y + v3.y;
        acc.z += v0.z + v1.z + v2.z + v3.z;
        acc.w += v0.w + v1.w + v2.w + v3.w;
    }
    for (; k < deg; k++) {
        int j = g_col[s + k];
        float4 v = X[(size_t)j * 64 + t];
        acc.x += v.x; acc.y += v.y; acc.z += v.z; acc.w += v.w;
    }
    float4 bb = ((const float4*)bsgc)[t];
    acc.x += bb.x; acc.y += bb.y; acc.z += bb.z; acc.w += bb.w;
    ((float4*)out)[(size_t)row * 64 + t] = acc;
}

// =================== launch (two-stream fork-join graph) =====================
extern "C" void kernel_launch(void* const* d_in, const int* in_sizes, int n_in,
                              void* d_out, int out_size) {
    const float* x    = (const float*)d_in[0];
    const float* adj  = (const float*)d_in[1];
    const float* W1   = (const float*)d_in[2];
    const float* a1   = (const float*)d_in[3];
    const float* W2   = (const float*)d_in[4];
    const float* a2   = (const float*)d_in[5];
    const float* Wsgc = (const float*)d_in[6];
    const float* bsgc = (const float*)d_in[7];
    float* out = (float*)d_out;

    cudaStream_t s1;
    cudaStreamCreate(&s1);
    cudaEvent_t eStart, eConv, eAgg2;
    cudaEventCreateWithFlags(&eStart, cudaEventDisableTiming);
    cudaEventCreateWithFlags(&eConv,  cudaEventDisableTiming);
    cudaEventCreateWithFlags(&eAgg2,  cudaEventDisableTiming);

    // fork: s1 joins the capture via eStart
    cudaEventRecord(eStart, 0);
    cudaStreamWaitEvent(s1, eStart, 0);

    // stream s1: CSR build (parallel with conv)
    k_csr<<<512, 256, 0, s1>>>(adj);

    // stream 0: conversions + fused x@W1 front-end, then tensor GEMM
    k_conv<<<2560, 256>>>(x, Wsgc, W1, a1);
    cudaEventRecord(eConv, 0);
    k_gemm<<<dim3(32, 4), 256>>>();

    // stream s1: GAT chain (needs conv outputs + CSR), overlaps GEMM
    cudaStreamWaitEvent(s1, eConv, 0);
    k_agg1<<<512, 256, 0, s1>>>(W2, a2);
    k_agg2<<<512, 256, 0, s1>>>();
    cudaEventRecord(eAgg2, s1);

    // join + SpMM chain on stream 0
    cudaStreamWaitEvent(0, eAgg2, 0);
    k_spmm1<<<NN, 128>>>(bsgc, out);
    k_spmm2<<<NN, 64>>>();
    k_spmm3<<<NN, 64>>>(bsgc, out);

    cudaEventDestroy(eStart);
    cudaEventDestroy(eConv);
    cudaEventDestroy(eAgg2);
    cudaStreamDestroy(s1);
}

// round 11
// speedup vs baseline: 1.2384x; 1.0392x over previous
#include <cuda_runtime.h>
#include <cuda_bf16.h>
#include <math.h>
#include <stdint.h>

#define NN     4096
#define INF    512
#define HID    8
#define OUTF   256
#define DEGMAX 128
#define LAMBDA_ 0.7f

// ---------------- scratch (static device globals; no allocation) -------------
__device__ int   g_deg[NN];
__device__ int   g_col[NN * DEGMAX];
__device__ __nv_bfloat16 g_xc[NN * 1536];     // [x_hi | x_lo | x_hi]
__device__ __nv_bfloat16 g_bp[512 * 1536];    // B'[n][k]
__device__ float g_z0[NN * 512];              // [u = x@Wa | v = x@Wc]
__device__ float g_y1v[NN * 256];
__device__ float g_y2[NN * 256];
__device__ float g_q[NN * HID];               // e1 ⊙ h   (layer-1 gather vector)
__device__ float g_e1[NN];                    // exp(dst1)
__device__ float g_q2[NN];                    // e2 * hp  (layer-2 gather scalar)
__device__ float g_e2[NN];                    // exp(dst2)
__device__ float g_mask[NN];
__device__ int   g_need2[NN];
__device__ int   g_list[NN];
__device__ int   g_n0;

__device__ __forceinline__ float elu1(float v) {
    return v > 0.0f ? v : (expf(v) - 1.0f);
}

// ======= merged conversion + fused x@W1 GAT front-end ========================
__global__ void k_conv(const float* __restrict__ x, const float* __restrict__ Wsgc,
                       const float* __restrict__ W1, const float* __restrict__ a1) {
    int t = threadIdx.x;
    if (blockIdx.x < 2048) {
        int idx = blockIdx.x * 256 + t;
        int m = idx >> 7, c4 = idx & 127;
        float4 v = ((const float4*)x)[idx];
        __nv_bfloat16 h0 = __float2bfloat16(v.x), h1 = __float2bfloat16(v.y);
        __nv_bfloat16 h2 = __float2bfloat16(v.z), h3 = __float2bfloat16(v.w);
        __nv_bfloat16 l0 = __float2bfloat16(v.x - __bfloat162float(h0));
        __nv_bfloat16 l1 = __float2bfloat16(v.y - __bfloat162float(h1));
        __nv_bfloat16 l2 = __float2bfloat16(v.z - __bfloat162float(h2));
        __nv_bfloat16 l3 = __float2bfloat16(v.w - __bfloat162float(h3));
        __nv_bfloat162 hA, hB, lA, lB;
        hA.x = h0; hA.y = h1; hB.x = h2; hB.y = h3;
        lA.x = l0; lA.y = l1; lB.x = l2; lB.y = l3;
        __nv_bfloat162* dst = (__nv_bfloat162*)(g_xc + (size_t)m * 1536 + c4 * 4);
        dst[0] = hA; dst[1] = hB;            // seg 0: hi
        dst[256] = lA; dst[257] = lB;        // seg 1: lo
        dst[512] = hA; dst[513] = hB;        // seg 2: hi

        // ---- fused x@W1 partial (W1 is 16KB, L1-resident) ----
        float acc[HID];
#pragma unroll
        for (int f = 0; f < HID; f++) acc[f] = 0.0f;
        const float4* W14 = (const float4*)W1;
#pragma unroll
        for (int e = 0; e < 4; e++) {
            float xv = (e == 0) ? v.x : (e == 1) ? v.y : (e == 2) ? v.z : v.w;
            float4 w0 = W14[(c4 * 4 + e) * 2];
            float4 w1 = W14[(c4 * 4 + e) * 2 + 1];
            acc[0] += xv * w0.x; acc[1] += xv * w0.y;
            acc[2] += xv * w0.z; acc[3] += xv * w0.w;
            acc[4] += xv * w1.x; acc[5] += xv * w1.y;
            acc[6] += xv * w1.z; acc[7] += xv * w1.w;
        }
#pragma unroll
        for (int f = 0; f < HID; f++)
            for (int o = 16; o; o >>= 1) acc[f] += __shfl_xor_sync(~0u, acc[f], o);
        __shared__ float part[8][HID];
        __shared__ float hs[2][HID];
        __shared__ float hrow[2][HID];
        __shared__ float se[2];
        int w = t >> 5, lane = t & 31;
        if (lane == 0) {
#pragma unroll
            for (int f = 0; f < HID; f++) part[w][f] = acc[f];
        }
        __syncthreads();
        if (t < 16) {    // warps 0-3 -> local row 0, warps 4-7 -> local row 1
            int lr = t >> 3, f = t & 7;
            float s = part[lr * 4 + 0][f] + part[lr * 4 + 1][f] +
                      part[lr * 4 + 2][f] + part[lr * 4 + 3][f];
            hs[lr][f] = s;
            hrow[lr][f] = s * a1[HID + f];
        }
        __syncthreads();
        if (t < 2) {
            float d = 0.0f;
#pragma unroll
            for (int f = 0; f < HID; f++) d += hrow[t][f];
            float e = expf(d);
            g_e1[blockIdx.x * 2 + t] = e;
            se[t] = e;
        }
        __syncthreads();
        if (t < 16) {    // q = e1 * h  (fused gather vector for agg1)
            int lr = t >> 3, f = t & 7;
            g_q[(blockIdx.x * 2 + lr) * HID + f] = se[lr] * hs[lr][f];
        }
    } else {
        int n = blockIdx.x - 2048;
#pragma unroll
        for (int i = 0; i < 6; i++) {
            int k = t + i * 256;
            int kk = k & 511, seg = k >> 9;
            float wf = (n < 256) ? Wsgc[(size_t)kk * OUTF + n]
                                 : Wsgc[(size_t)(1024 + kk) * OUTF + (n - 256)];
            __nv_bfloat16 h = __float2bfloat16(wf);
            __nv_bfloat16 o = (seg == 2) ? __float2bfloat16(wf - __bfloat162float(h)) : h;
            g_bp[(size_t)n * 1536 + k] = o;
        }
    }
}

// =================== mma.sync GEMM: Z0 = Xc @ Bp^T ===========================
#define GBM 128
#define GBN 128

__device__ __forceinline__ uint32_t smem_u32(const void* p) {
    uint32_t a;
    asm("{ .reg .u64 t; cvta.to.shared.u64 t, %1; cvt.u32.u64 %0, t; }"
        : "=r"(a) : "l"(p));
    return a;
}
__device__ __forceinline__ void ldmx4(uint32_t* r, uint32_t addr) {
    asm volatile("ldmatrix.sync.aligned.m8n8.x4.shared.b16 {%0,%1,%2,%3}, [%4];"
                 : "=r"(r[0]), "=r"(r[1]), "=r"(r[2]), "=r"(r[3]) : "r"(addr));
}
__device__ __forceinline__ void mma16816(float* d, const uint32_t* a, const uint32_t* b) {
    asm volatile(
        "mma.sync.aligned.m16n8k16.row.col.f32.bf16.bf16.f32 "
        "{%0,%1,%2,%3}, {%4,%5,%6,%7}, {%8,%9}, {%0,%1,%2,%3};"
        : "+f"(d[0]), "+f"(d[1]), "+f"(d[2]), "+f"(d[3])
        : "r"(a[0]), "r"(a[1]), "r"(a[2]), "r"(a[3]), "r"(b[0]), "r"(b[1]));
}

__global__ void __launch_bounds__(256, 1) k_gemm() {
    __shared__ uint4 As[2][GBM * 4];
    __shared__ uint4 Bs[2][GBN * 4];

    int t = threadIdx.x, wid = t >> 5, lane = t & 31;
    int bm = blockIdx.x * GBM, bn = blockIdx.y * GBN;
    int wm = (wid >> 2) * 64;
    int wn = (wid & 3) * 32;

    const __nv_bfloat16* Ag = g_xc + (size_t)bm * 1536;
    const __nv_bfloat16* Bg = g_bp + (size_t)bn * 1536;

    int la_m[2], la_c[2];
#pragma unroll
    for (int q = 0; q < 2; q++) {
        int idx = t + q * 256;
        la_m[q] = idx >> 2;
        la_c[q] = idx & 3;
    }

    float acc[4][4][4];
#pragma unroll
    for (int i = 0; i < 4; i++)
#pragma unroll
        for (int j = 0; j < 4; j++)
#pragma unroll
            for (int r = 0; r < 4; r++) acc[i][j][r] = 0.0f;

    int a_r = lane & 15, a_cc = lane >> 4;
    int b_r = (lane & 7) + ((lane >> 4) & 1) * 8, b_cc = (lane >> 3) & 1;

    uint4 ra[2], rb[2];
#pragma unroll
    for (int q = 0; q < 2; q++) {
        ra[q] = *(const uint4*)(Ag + (size_t)la_m[q] * 1536 + la_c[q] * 8);
        rb[q] = *(const uint4*)(Bg + (size_t)la_m[q] * 1536 + la_c[q] * 8);
    }
#pragma unroll
    for (int q = 0; q < 2; q++) {
        int m = la_m[q], c = la_c[q];
        int sw = c ^ ((m >> 1) & 3);
        As[0][m * 4 + sw] = ra[q];
        Bs[0][m * 4 + sw] = rb[q];
    }
    __syncthreads();

    for (int kc = 0; kc < 48; kc++) {
        int cur = kc & 1;
        if (kc < 47) {
#pragma unroll
            for (int q = 0; q < 2; q++) {
                size_t o = (size_t)la_m[q] * 1536 + (kc + 1) * 32 + la_c[q] * 8;
                ra[q] = *(const uint4*)(Ag + o);
                rb[q] = *(const uint4*)(Bg + o);
            }
        }
        uint32_t as_base = smem_u32(&As[cur][0]);
        uint32_t bs_base = smem_u32(&Bs[cur][0]);
#pragma unroll
        for (int kk = 0; kk < 2; kk++) {
            int c0 = kk * 2;
            uint32_t afr[4][4], bfr[2][4];
#pragma unroll
            for (int mi = 0; mi < 4; mi++) {
                int m = wm + mi * 16 + a_r;
                int c = (c0 + a_cc) ^ ((m >> 1) & 3);
                ldmx4(afr[mi], as_base + m * 64 + c * 16);
            }
#pragma unroll
            for (int nj = 0; nj < 2; nj++) {
                int n = wn + nj * 16 + b_r;
                int c = (c0 + b_cc) ^ ((n >> 1) & 3);
                ldmx4(bfr[nj], bs_base + n * 64 + c * 16);
            }
#pragma unroll
            for (int mi = 0; mi < 4; mi++) {
#pragma unroll
                for (int nj = 0; nj < 4; nj++) {
                    mma16816(acc[mi][nj], afr[mi], &bfr[nj >> 1][(nj & 1) * 2]);
                }
            }
        }
        if (kc < 47) {
#pragma unroll
            for (int q = 0; q < 2; q++) {
                int m = la_m[q], c = la_c[q];
                int sw = c ^ ((m >> 1) & 3);
                As[cur ^ 1][m * 4 + sw] = ra[q];
                Bs[cur ^ 1][m * 4 + sw] = rb[q];
            }
            __syncthreads();
        }
    }

#pragma unroll
    for (int mi = 0; mi < 4; mi++) {
        int r0 = bm + wm + mi * 16 + (lane >> 2);
#pragma unroll
        for (int nj = 0; nj < 4; nj++) {
            int c = bn + wn + nj * 8 + (lane & 3) * 2;
            *(float2*)(g_z0 + (size_t)r0 * 512 + c) =
                make_float2(acc[mi][nj][0], acc[mi][nj][1]);
            *(float2*)(g_z0 + (size_t)(r0 + 8) * 512 + c) =
                make_float2(acc[mi][nj][2], acc[mi][nj][3]);
        }
    }
}

// =================== one-pass padded CSR (float4 loads) + init ===============
__global__ void k_csr(const float* __restrict__ adj) {
    if (threadIdx.x < 8) g_need2[blockIdx.x * 8 + threadIdx.x] = 0;
    if (blockIdx.x == 0 && threadIdx.x == 0) g_n0 = 0;

    int row = blockIdx.x * 8 + (threadIdx.x >> 5);
    int lane = threadIdx.x & 31;
    const float4* a = (const float4*)(adj + (size_t)row * NN);
    int base = row * DEGMAX, cnt = 0;
    unsigned below = (1u << lane) - 1u;
#pragma unroll 2
    for (int j0 = 0; j0 < 1024; j0 += 32) {
        float4 v = a[j0 + lane];
        unsigned b0 = __ballot_sync(~0u, v.x > 0.5f);
        unsigned b1 = __ballot_sync(~0u, v.y > 0.5f);
        unsigned b2 = __ballot_sync(~0u, v.z > 0.5f);
        unsigned b3 = __ballot_sync(~0u, v.w > 0.5f);
        int p = base + cnt +
                __popc(b0 & below) + __popc(b1 & below) +
                __popc(b2 & below) + __popc(b3 & below);
        int col0 = (j0 + lane) * 4;
        if (v.x > 0.5f) g_col[p++] = col0 + 0;
        if (v.y > 0.5f) g_col[p++] = col0 + 1;
        if (v.z > 0.5f) g_col[p++] = col0 + 2;
        if (v.w > 0.5f) g_col[p++] = col0 + 3;
        cnt += __popc(b0) + __popc(b1) + __popc(b2) + __popc(b3);
    }
    if (lane == 0) g_deg[row] = cnt;
}

// ---- block-level sum of a 4096-float array (deterministic) ------------------
__device__ __forceinline__ float block_sum_4096(const float* arr, float* red) {
    int t = threadIdx.x, lane = t & 31, w = t >> 5;
    const float4* A4 = (const float4*)arr;
    float s = 0.0f;
#pragma unroll
    for (int q = 0; q < 4; q++) {
        float4 v = A4[t + q * 256];
        s += (v.x + v.y) + (v.z + v.w);
    }
    for (int o = 16; o; o >>= 1) s += __shfl_xor_sync(~0u, s, o);
    if (lane == 0) red[w] = s;
    __syncthreads();
    float S = ((red[0] + red[1]) + (red[2] + red[3])) +
              ((red[4] + red[5]) + (red[6] + red[7]));
    return S;
}

// ------- GAT agg layer 1: gather q (2xfloat4/neighbor), emit e2, q2 ----------
__global__ void k_agg1(const float* __restrict__ W2, const float* __restrict__ a2) {
    __shared__ float red[8];
    float inv = 1.0f / block_sum_4096(g_e1, red);

    int row = blockIdx.x * 8 + (threadIdx.x >> 5);
    int lane = threadIdx.x & 31;
    int s = row * DEGMAX, deg = g_deg[row];
    float4 a0 = make_float4(0.f, 0.f, 0.f, 0.f);
    float4 a1v = make_float4(0.f, 0.f, 0.f, 0.f);
    for (int k = lane; k < deg; k += 32) {
        int j = g_col[s + k];
        const float4* q = (const float4*)(g_q + j * HID);
        float4 q0 = q[0], q1 = q[1];
        a0.x += q0.x; a0.y += q0.y; a0.z += q0.z; a0.w += q0.w;
        a1v.x += q1.x; a1v.y += q1.y; a1v.z += q1.z; a1v.w += q1.w;
    }
#pragma unroll
    for (int o = 16; o; o >>= 1) {
        a0.x += __shfl_xor_sync(~0u, a0.x, o);
        a0.y += __shfl_xor_sync(~0u, a0.y, o);
        a0.z += __shfl_xor_sync(~0u, a0.z, o);
        a0.w += __shfl_xor_sync(~0u, a0.w, o);
        a1v.x += __shfl_xor_sync(~0u, a1v.x, o);
        a1v.y += __shfl_xor_sync(~0u, a1v.y, o);
        a1v.z += __shfl_xor_sync(~0u, a1v.z, o);
        a1v.w += __shfl_xor_sync(~0u, a1v.w, o);
    }
    if (lane == 0) {
        float hp = elu1(a0.x * inv) * W2[0] + elu1(a0.y * inv) * W2[1]
                 + elu1(a0.z * inv) * W2[2] + elu1(a0.w * inv) * W2[3]
                 + elu1(a1v.x * inv) * W2[4] + elu1(a1v.y * inv) * W2[5]
                 + elu1(a1v.z * inv) * W2[6] + elu1(a1v.w * inv) * W2[7];
        float e2 = expf(hp * a2[1]);
        g_e2[row] = e2;
        g_q2[row] = e2 * hp;
    }
}

// ------- GAT agg layer 2 (scalar q2 gather) + mask + hop-2/3 flags -----------
__global__ void k_agg2() {
    __shared__ float red[8];
    float inv = 1.0f / block_sum_4096(g_e2, red);

    int row = blockIdx.x * 8 + (threadIdx.x >> 5);
    int lane = threadIdx.x & 31;
    int s = row * DEGMAX, deg = g_deg[row];
    float acc = 0.0f;
    for (int k = lane; k < deg; k += 32) {
        acc += g_q2[g_col[s + k]];
    }
    for (int o = 16; o; o >>= 1) acc += __shfl_xor_sync(~0u, acc, o);
    float mask = 0.0f;
    if (lane == 0) {
        float sc = elu1(acc * inv);
        mask = sc > LAMBDA_ ? 1.0f : 0.0f;
        g_mask[row] = mask;
        if (mask == 0.0f) {
            int slot = atomicAdd(&g_n0, 1);
            g_list[slot] = row;
        }
    }
    mask = __shfl_sync(~0u, mask, 0);
    if (mask == 0.0f) {
        for (int k = lane; k < deg; k += 32) g_need2[g_col[s + k]] = 1;
    }
}

// =================== SpMMs ====================================================
// hop1 v-half: y1v = A@v  (mask-independent -> overlaps the agg chain)
__global__ void k_spmm1v() {
    int row = blockIdx.x;
    int t = threadIdx.x;               // 64
    int s = row * DEGMAX, deg = g_deg[row];
    const float4* X = (const float4*)g_z0;
    int cofs = 64 + t;                 // v columns
    float4 acc = make_float4(0.f, 0.f, 0.f, 0.f);
    int k = 0;
    for (; k + 3 < deg; k += 4) {
        int j0 = g_col[s + k], j1 = g_col[s + k + 1];
        int j2 = g_col[s + k + 2], j3 = g_col[s + k + 3];
        float4 v0 = X[(size_t)j0 * 128 + cofs];
        float4 v1 = X[(size_t)j1 * 128 + cofs];
        float4 v2 = X[(size_t)j2 * 128 + cofs];
        float4 v3 = X[(size_t)j3 * 128 + cofs];
        acc.x += v0.x + v1.x + v2.x + v3.x;
        acc.y += v0.y + v1.y + v2.y + v3.y;
        acc.z += v0.z + v1.z + v2.z + v3.z;
        acc.w += v0.w + v1.w + v2.w + v3.w;
    }
    for (; k < deg; k++) {
        int j = g_col[s + k];
        float4 v = X[(size_t)j * 128 + cofs];
        acc.x += v.x; acc.y += v.y; acc.z += v.z; acc.w += v.w;
    }
    ((float4*)g_y1v)[(size_t)row * 64 + t] = acc;
}

// hop1 u-half: out = A@u + bias, mask=1 rows only
__global__ void k_spmm1u(const float* __restrict__ bsgc, float* __restrict__ out) {
    int row = blockIdx.x;
    if (g_mask[row] == 0.0f) return;
    int t = threadIdx.x;               // 64
    int s = row * DEGMAX, deg = g_deg[row];
    const float4* X = (const float4*)g_z0;
    float4 acc = make_float4(0.f, 0.f, 0.f, 0.f);
    int k = 0;
    for (; k + 3 < deg; k += 4) {
        int j0 = g_col[s + k], j1 = g_col[s + k + 1];
        int j2 = g_col[s + k + 2], j3 = g_col[s + k + 3];
        float4 v0 = X[(size_t)j0 * 128 + t];
        float4 v1 = X[(size_t)j1 * 128 + t];
        float4 v2 = X[(size_t)j2 * 128 + t];
        float4 v3 = X[(size_t)j3 * 128 + t];
        acc.x += v0.x + v1.x + v2.x + v3.x;
        acc.y += v0.y + v1.y + v2.y + v3.y;
        acc.z += v0.z + v1.z + v2.z + v3.z;
        acc.w += v0.w + v1.w + v2.w + v3.w;
    }
    for (; k < deg; k++) {
        int j = g_col[s + k];
        float4 v = X[(size_t)j * 128 + t];
        acc.x += v.x; acc.y += v.y; acc.z += v.z; acc.w += v.w;
    }
    float4 b = ((const float4*)bsgc)[t];
    acc.x += b.x; acc.y += b.y; acc.z += b.z; acc.w += b.w;
    ((float4*)out)[(size_t)row * 64 + t] = acc;
}

// hop2: y2 = A@y1v, only rows that neighbor a masked-0 row
__global__ void k_spmm2() {
    int row = blockIdx.x;
    if (!g_need2[row]) return;
    int t = threadIdx.x;               // 64
    int s = row * DEGMAX, deg = g_deg[row];
    const float4* X = (const float4*)g_y1v;
    float4 acc = make_float4(0.f, 0.f, 0.f, 0.f);
    int k = 0;
    for (; k + 3 < deg; k += 4) {
        int j0 = g_col[s + k], j1 = g_col[s + k + 1];
        int j2 = g_col[s + k + 2], j3 = g_col[s + k + 3];
        float4 v0 = X[(size_t)j0 * 64 + t];
        float4 v1 = X[(size_t)j1 * 64 + t];
        float4 v2 = X[(size_t)j2 * 64 + t];
        float4 v3 = X[(size_t)j3 * 64 + t];
        acc.x += v0.x + v1.x + v2.x + v3.x;
        acc.y += v0.y + v1.y + v2.y + v3.y;
        acc.z += v0.z + v1.z + v2.z + v3.z;
        acc.w += v0.w + v1.w + v2.w + v3.w;
    }
    for (; k < deg; k++) {
        int j = g_col[s + k];
        float4 v = X[(size_t)j * 64 + t];
        acc.x += v.x; acc.y += v.y; acc.z += v.z; acc.w += v.w;
    }
    ((float4*)g_y2)[(size_t)row * 64 + t] = acc;
}

// hop3: out = A@y2 + bias, only masked-0 rows (compacted list)
__global__ void k_spmm3(const float* __restrict__ bsgc, float* __restrict__ out) {
    int b = blockIdx.x;
    if (b >= g_n0) return;
    int row = g_list[b];
    int t = threadIdx.x;               // 64
    int s = row * DEGMAX, deg = g_deg[row];
    const float4* X = (const float4*)g_y2;
    float4 acc = make_float4(0.f, 0.f, 0.f, 0.f);
    int k = 0;
    for (; k + 3 < deg; k += 4) {
        int j0 = g_col[s + k], j1 = g_col[s + k + 1];
        int j2 = g_col[s + k + 2], j3 = g_col[s + k + 3];
        float4 v0 = X[(size_t)j0 * 64 + t];
        float4 v1 = X[(size_t)j1 * 64 + t];
        float4 v2 = X[(size_t)j2 * 64 + t];
        float4 v3 = X[(size_t)j3 * 64 + t];
        acc.x += v0.x + v1.x + v2.x + v3.x;
        acc.y += v0.y + v1.y + v2.y + v3.y;
        acc.z += v0.z + v1.z + v2.z + v3.z;
        acc.w += v0.w + v1.w + v2.w + v3.w;
    }
    for (; k < deg; k++) {
        int j = g_col[s + k];
        float4 v = X[(size_t)j * 64 + t];
        acc.x += v.x; acc.y += v.y; acc.z += v.z; acc.w += v.w;
    }
    float4 bb = ((const float4*)bsgc)[t];
    acc.x += bb.x; acc.y += bb.y; acc.z += bb.z; acc.w += bb.w;
    ((float4*)out)[(size_t)row * 64 + t] = acc;
}

// =================== launch (two-stream fork-join graph) =====================
extern "C" void kernel_launch(void* const* d_in, const int* in_sizes, int n_in,
                              void* d_out, int out_size) {
    const float* x    = (const float*)d_in[0];
    const float* adj  = (const float*)d_in[1];
    const float* W1   = (const float*)d_in[2];
    const float* a1   = (const float*)d_in[3];
    const float* W2   = (const float*)d_in[4];
    const float* a2   = (const float*)d_in[5];
    const float* Wsgc = (const float*)d_in[6];
    const float* bsgc = (const float*)d_in[7];
    float* out = (float*)d_out;

    cudaStream_t s1;
    cudaStreamCreate(&s1);
    cudaEvent_t eStart, eConv, eGemm, eAgg2, eU;
    cudaEventCreateWithFlags(&eStart, cudaEventDisableTiming);
    cudaEventCreateWithFlags(&eConv,  cudaEventDisableTiming);
    cudaEventCreateWithFlags(&eGemm,  cudaEventDisableTiming);
    cudaEventCreateWithFlags(&eAgg2,  cudaEventDisableTiming);
    cudaEventCreateWithFlags(&eU,     cudaEventDisableTiming);

    // fork: s1 joins the capture via eStart
    cudaEventRecord(eStart, 0);
    cudaStreamWaitEvent(s1, eStart, 0);

    // stream s1: CSR build (parallel with conv)
    k_csr<<<512, 256, 0, s1>>>(adj);

    // stream 0: conversions + fused x@W1 front-end, then tensor GEMM, then A@v
    k_conv<<<2560, 256>>>(x, Wsgc, W1, a1);
    cudaEventRecord(eConv, 0);
    k_gemm<<<dim3(32, 4), 256>>>();
    cudaEventRecord(eGemm, 0);
    k_spmm1v<<<NN, 64>>>();

    // stream s1: GAT chain (needs conv + CSR), overlaps gemm/spmm1v
    cudaStreamWaitEvent(s1, eConv, 0);
    k_agg1<<<512, 256, 0, s1>>>(W2, a2);
    k_agg2<<<512, 256, 0, s1>>>();
    cudaEventRecord(eAgg2, s1);

    // stream s1: u-half of hop1 (needs gemm + mask), concurrent with spmm2
    cudaStreamWaitEvent(s1, eGemm, 0);
    k_spmm1u<<<NN, 64, 0, s1>>>(bsgc, out);
    cudaEventRecord(eU, s1);

    // stream 0: hop2 (needs y1v + need2), hop3
    cudaStreamWaitEvent(0, eAgg2, 0);
    k_spmm2<<<NN, 64>>>();
    k_spmm3<<<NN, 64>>>(bsgc, out);

    // join s1 back before capture end
    cudaStreamWaitEvent(0, eU, 0);

    cudaEventDestroy(eStart);
    cudaEventDestroy(eConv);
    cudaEventDestroy(eGemm);
    cudaEventDestroy(eAgg2);
    cudaEventDestroy(eU);
    cudaStreamDestroy(s1);
}

// round 12
// speedup vs baseline: 1.3153x; 1.0621x over previous
#include <cuda_runtime.h>
#include <cuda_bf16.h>
#include <cuda_fp16.h>
#include <math.h>
#include <stdint.h>

#define NN     4096
#define INF    512
#define HID    8
#define OUTF   256
#define DEGMAX 128
#define LAMBDA_ 0.7f

// ---------------- scratch (static device globals; no allocation) -------------
__device__ int   g_deg[NN];
__device__ int   g_col[NN * DEGMAX];
__device__ __nv_bfloat16 g_xc[NN * 1024];     // [x_hi | x_lo]
__device__ __nv_bfloat16 g_bp[512 * 1536];    // B'[n][k] = [w_hi | w_hi | w_lo]
__device__ __half g_z0h[NN * 512];            // fp16 [u | v]
__device__ __half g_y1vh[NN * 256];           // fp16 A@v
__device__ __half g_y2h[NN * 256];            // fp16 A^2@v
__device__ float g_q[NN * HID];               // e1 ⊙ h
__device__ float g_e1[NN];
__device__ float g_q2[NN];                    // e2 * hp
__device__ float g_e2[NN];
__device__ float g_mask[NN];
__device__ int   g_need2[NN];
__device__ int   g_list[NN];
__device__ int   g_n0;

__device__ __forceinline__ float elu1(float v) {
    return v > 0.0f ? v : (expf(v) - 1.0f);
}

// unpack half8 (uint4) and accumulate into 8 fp32 lanes
__device__ __forceinline__ void acc8(float* a, uint4 p) {
    __half2 h0 = *(__half2*)&p.x, h1 = *(__half2*)&p.y;
    __half2 h2 = *(__half2*)&p.z, h3 = *(__half2*)&p.w;
    float2 f;
    f = __half22float2(h0); a[0] += f.x; a[1] += f.y;
    f = __half22float2(h1); a[2] += f.x; a[3] += f.y;
    f = __half22float2(h2); a[4] += f.x; a[5] += f.y;
    f = __half22float2(h3); a[6] += f.x; a[7] += f.y;
}

// ======= merged conversion + fused x@W1 GAT front-end ========================
__global__ void k_conv(const float* __restrict__ x, const float* __restrict__ Wsgc,
                       const float* __restrict__ W1, const float* __restrict__ a1) {
    int t = threadIdx.x;
    if (blockIdx.x < 2048) {
        int idx = blockIdx.x * 256 + t;
        int m = idx >> 7, c4 = idx & 127;
        float4 v = ((const float4*)x)[idx];
        __nv_bfloat16 h0 = __float2bfloat16(v.x), h1 = __float2bfloat16(v.y);
        __nv_bfloat16 h2 = __float2bfloat16(v.z), h3 = __float2bfloat16(v.w);
        __nv_bfloat16 l0 = __float2bfloat16(v.x - __bfloat162float(h0));
        __nv_bfloat16 l1 = __float2bfloat16(v.y - __bfloat162float(h1));
        __nv_bfloat16 l2 = __float2bfloat16(v.z - __bfloat162float(h2));
        __nv_bfloat16 l3 = __float2bfloat16(v.w - __bfloat162float(h3));
        __nv_bfloat162 hA, hB, lA, lB;
        hA.x = h0; hA.y = h1; hB.x = h2; hB.y = h3;
        lA.x = l0; lA.y = l1; lB.x = l2; lB.y = l3;
        __nv_bfloat162* dst = (__nv_bfloat162*)(g_xc + (size_t)m * 1024 + c4 * 4);
        dst[0] = hA; dst[1] = hB;            // seg 0: hi
        dst[256] = lA; dst[257] = lB;        // seg 1: lo (+512 elems)

        // ---- fused x@W1 partial (W1 is 16KB, L1-resident) ----
        float acc[HID];
#pragma unroll
        for (int f = 0; f < HID; f++) acc[f] = 0.0f;
        const float4* W14 = (const float4*)W1;
#pragma unroll
        for (int e = 0; e < 4; e++) {
            float xv = (e == 0) ? v.x : (e == 1) ? v.y : (e == 2) ? v.z : v.w;
            float4 w0 = W14[(c4 * 4 + e) * 2];
            float4 w1 = W14[(c4 * 4 + e) * 2 + 1];
            acc[0] += xv * w0.x; acc[1] += xv * w0.y;
            acc[2] += xv * w0.z; acc[3] += xv * w0.w;
            acc[4] += xv * w1.x; acc[5] += xv * w1.y;
            acc[6] += xv * w1.z; acc[7] += xv * w1.w;
        }
#pragma unroll
        for (int f = 0; f < HID; f++)
            for (int o = 16; o; o >>= 1) acc[f] += __shfl_xor_sync(~0u, acc[f], o);
        __shared__ float part[8][HID];
        __shared__ float hs[2][HID];
        __shared__ float hrow[2][HID];
        __shared__ float se[2];
        int w = t >> 5, lane = t & 31;
        if (lane == 0) {
#pragma unroll
            for (int f = 0; f < HID; f++) part[w][f] = acc[f];
        }
        __syncthreads();
        if (t < 16) {
            int lr = t >> 3, f = t & 7;
            float s = part[lr * 4 + 0][f] + part[lr * 4 + 1][f] +
                      part[lr * 4 + 2][f] + part[lr * 4 + 3][f];
            hs[lr][f] = s;
            hrow[lr][f] = s * a1[HID + f];
        }
        __syncthreads();
        if (t < 2) {
            float d = 0.0f;
#pragma unroll
            for (int f = 0; f < HID; f++) d += hrow[t][f];
            float e = expf(d);
            g_e1[blockIdx.x * 2 + t] = e;
            se[t] = e;
        }
        __syncthreads();
        if (t < 16) {
            int lr = t >> 3, f = t & 7;
            g_q[(blockIdx.x * 2 + lr) * HID + f] = se[lr] * hs[lr][f];
        }
    } else {
        int n = blockIdx.x - 2048;
#pragma unroll
        for (int i = 0; i < 6; i++) {
            int k = t + i * 256;
            int kk = k & 511, seg = k >> 9;
            float wf = (n < 256) ? Wsgc[(size_t)kk * OUTF + n]
                                 : Wsgc[(size_t)(1024 + kk) * OUTF + (n - 256)];
            __nv_bfloat16 h = __float2bfloat16(wf);
            __nv_bfloat16 o = (seg == 2) ? __float2bfloat16(wf - __bfloat162float(h)) : h;
            g_bp[(size_t)n * 1536 + k] = o;
        }
    }
}

// =================== mma.sync GEMM: Z0 = Xc @ Bp^T (fp16 out) ================
#define GBM 128
#define GBN 128

__device__ __forceinline__ uint32_t smem_u32(const void* p) {
    uint32_t a;
    asm("{ .reg .u64 t; cvta.to.shared.u64 t, %1; cvt.u32.u64 %0, t; }"
        : "=r"(a) : "l"(p));
    return a;
}
__device__ __forceinline__ void ldmx4(uint32_t* r, uint32_t addr) {
    asm volatile("ldmatrix.sync.aligned.m8n8.x4.shared.b16 {%0,%1,%2,%3}, [%4];"
                 : "=r"(r[0]), "=r"(r[1]), "=r"(r[2]), "=r"(r[3]) : "r"(addr));
}
__device__ __forceinline__ void mma16816(float* d, const uint32_t* a, const uint32_t* b) {
    asm volatile(
        "mma.sync.aligned.m16n8k16.row.col.f32.bf16.bf16.f32 "
        "{%0,%1,%2,%3}, {%4,%5,%6,%7}, {%8,%9}, {%0,%1,%2,%3};"
        : "+f"(d[0]), "+f"(d[1]), "+f"(d[2]), "+f"(d[3])
        : "r"(a[0]), "r"(a[1]), "r"(a[2]), "r"(a[3]), "r"(b[0]), "r"(b[1]));
}

__global__ void __launch_bounds__(256, 1) k_gemm() {
    __shared__ uint4 As[2][GBM * 4];
    __shared__ uint4 Bs[2][GBN * 4];

    int t = threadIdx.x, wid = t >> 5, lane = t & 31;
    int bm = blockIdx.x * GBM, bn = blockIdx.y * GBN;
    int wm = (wid >> 2) * 64;
    int wn = (wid & 3) * 32;

    const __nv_bfloat16* Ag = g_xc + (size_t)bm * 1024;   // 1024-wide A
    const __nv_bfloat16* Bg = g_bp + (size_t)bn * 1536;

    int la_m[2], la_c[2];
#pragma unroll
    for (int q = 0; q < 2; q++) {
        int idx = t + q * 256;
        la_m[q] = idx >> 2;
        la_c[q] = idx & 3;
    }

    float acc[4][4][4];
#pragma unroll
    for (int i = 0; i < 4; i++)
#pragma unroll
        for (int j = 0; j < 4; j++)
#pragma unroll
            for (int r = 0; r < 4; r++) acc[i][j][r] = 0.0f;

    int a_r = lane & 15, a_cc = lane >> 4;
    int b_r = (lane & 7) + ((lane >> 4) & 1) * 8, b_cc = (lane >> 3) & 1;

    uint4 ra[2], rb[2];
#pragma unroll
    for (int q = 0; q < 2; q++) {
        ra[q] = *(const uint4*)(Ag + (size_t)la_m[q] * 1024 + la_c[q] * 8);
        rb[q] = *(const uint4*)(Bg + (size_t)la_m[q] * 1536 + la_c[q] * 8);
    }
#pragma unroll
    for (int q = 0; q < 2; q++) {
        int m = la_m[q], c = la_c[q];
        int sw = c ^ ((m >> 1) & 3);
        As[0][m * 4 + sw] = ra[q];
        Bs[0][m * 4 + sw] = rb[q];
    }
    __syncthreads();

    for (int kc = 0; kc < 48; kc++) {
        int cur = kc & 1;
        if (kc < 47) {
            int akc = (kc + 1 < 32) ? (kc + 1) : (kc + 1 - 32);  // seg2 -> hi again
#pragma unroll
            for (int q = 0; q < 2; q++) {
                ra[q] = *(const uint4*)(Ag + (size_t)la_m[q] * 1024 + akc * 32 + la_c[q] * 8);
                rb[q] = *(const uint4*)(Bg + (size_t)la_m[q] * 1536 + (kc + 1) * 32 + la_c[q] * 8);
            }
        }
        uint32_t as_base = smem_u32(&As[cur][0]);
        uint32_t bs_base = smem_u32(&Bs[cur][0]);
#pragma unroll
        for (int kk = 0; kk < 2; kk++) {
            int c0 = kk * 2;
            uint32_t afr[4][4], bfr[2][4];
#pragma unroll
            for (int mi = 0; mi < 4; mi++) {
                int m = wm + mi * 16 + a_r;
                int c = (c0 + a_cc) ^ ((m >> 1) & 3);
                ldmx4(afr[mi], as_base + m * 64 + c * 16);
            }
#pragma unroll
            for (int nj = 0; nj < 2; nj++) {
                int n = wn + nj * 16 + b_r;
                int c = (c0 + b_cc) ^ ((n >> 1) & 3);
                ldmx4(bfr[nj], bs_base + n * 64 + c * 16);
            }
#pragma unroll
            for (int mi = 0; mi < 4; mi++) {
#pragma unroll
                for (int nj = 0; nj < 4; nj++) {
                    mma16816(acc[mi][nj], afr[mi], &bfr[nj >> 1][(nj & 1) * 2]);
                }
            }
        }
        if (kc < 47) {
#pragma unroll
            for (int q = 0; q < 2; q++) {
                int m = la_m[q], c = la_c[q];
                int sw = c ^ ((m >> 1) & 3);
                As[cur ^ 1][m * 4 + sw] = ra[q];
                Bs[cur ^ 1][m * 4 + sw] = rb[q];
            }
            __syncthreads();
        }
    }

    // epilogue: fp16 stores
#pragma unroll
    for (int mi = 0; mi < 4; mi++) {
        int r0 = bm + wm + mi * 16 + (lane >> 2);
#pragma unroll
        for (int nj = 0; nj < 4; nj++) {
            int c = bn + wn + nj * 8 + (lane & 3) * 2;
            *(__half2*)(g_z0h + (size_t)r0 * 512 + c) =
                __floats2half2_rn(acc[mi][nj][0], acc[mi][nj][1]);
            *(__half2*)(g_z0h + (size_t)(r0 + 8) * 512 + c) =
                __floats2half2_rn(acc[mi][nj][2], acc[mi][nj][3]);
        }
    }
}

// =================== one-pass padded CSR (float4 loads) + init ===============
__global__ void k_csr(const float* __restrict__ adj) {
    if (threadIdx.x < 8) g_need2[blockIdx.x * 8 + threadIdx.x] = 0;
    if (blockIdx.x == 0 && threadIdx.x == 0) g_n0 = 0;

    int row = blockIdx.x * 8 + (threadIdx.x >> 5);
    int lane = threadIdx.x & 31;
    const float4* a = (const float4*)(adj + (size_t)row * NN);
    int base = row * DEGMAX, cnt = 0;
    unsigned below = (1u << lane) - 1u;
#pragma unroll 2
    for (int j0 = 0; j0 < 1024; j0 += 32) {
        float4 v = a[j0 + lane];
        unsigned b0 = __ballot_sync(~0u, v.x > 0.5f);
        unsigned b1 = __ballot_sync(~0u, v.y > 0.5f);
        unsigned b2 = __ballot_sync(~0u, v.z > 0.5f);
        unsigned b3 = __ballot_sync(~0u, v.w > 0.5f);
        int p = base + cnt +
                __popc(b0 & below) + __popc(b1 & below) +
                __popc(b2 & below) + __popc(b3 & below);
        int col0 = (j0 + lane) * 4;
        if (v.x > 0.5f) g_col[p++] = col0 + 0;
        if (v.y > 0.5f) g_col[p++] = col0 + 1;
        if (v.z > 0.5f) g_col[p++] = col0 + 2;
        if (v.w > 0.5f) g_col[p++] = col0 + 3;
        cnt += __popc(b0) + __popc(b1) + __popc(b2) + __popc(b3);
    }
    if (lane == 0) g_deg[row] = cnt;
}

// ---- block-level sum of a 4096-float array (deterministic) ------------------
__device__ __forceinline__ float block_sum_4096(const float* arr, float* red) {
    int t = threadIdx.x, lane = t & 31, w = t >> 5;
    const float4* A4 = (const float4*)arr;
    float s = 0.0f;
#pragma unroll
    for (int q = 0; q < 4; q++) {
        float4 v = A4[t + q * 256];
        s += (v.x + v.y) + (v.z + v.w);
    }
    for (int o = 16; o; o >>= 1) s += __shfl_xor_sync(~0u, s, o);
    if (lane == 0) red[w] = s;
    __syncthreads();
    float S = ((red[0] + red[1]) + (red[2] + red[3])) +
              ((red[4] + red[5]) + (red[6] + red[7]));
    return S;
}

// ------- GAT agg layer 1: gather q (2xfloat4/neighbor), emit e2, q2 ----------
__global__ void k_agg1(const float* __restrict__ W2, const float* __restrict__ a2) {
    __shared__ float red[8];
    float inv = 1.0f / block_sum_4096(g_e1, red);

    int row = blockIdx.x * 8 + (threadIdx.x >> 5);
    int lane = threadIdx.x & 31;
    int s = row * DEGMAX, deg = g_deg[row];
    float4 a0 = make_float4(0.f, 0.f, 0.f, 0.f);
    float4 a1v = make_float4(0.f, 0.f, 0.f, 0.f);
    for (int k = lane; k < deg; k += 32) {
        int j = g_col[s + k];
        const float4* q = (const float4*)(g_q + j * HID);
        float4 q0 = q[0], q1 = q[1];
        a0.x += q0.x; a0.y += q0.y; a0.z += q0.z; a0.w += q0.w;
        a1v.x += q1.x; a1v.y += q1.y; a1v.z += q1.z; a1v.w += q1.w;
    }
#pragma unroll
    for (int o = 16; o; o >>= 1) {
        a0.x += __shfl_xor_sync(~0u, a0.x, o);
        a0.y += __shfl_xor_sync(~0u, a0.y, o);
        a0.z += __shfl_xor_sync(~0u, a0.z, o);
        a0.w += __shfl_xor_sync(~0u, a0.w, o);
        a1v.x += __shfl_xor_sync(~0u, a1v.x, o);
        a1v.y += __shfl_xor_sync(~0u, a1v.y, o);
        a1v.z += __shfl_xor_sync(~0u, a1v.z, o);
        a1v.w += __shfl_xor_sync(~0u, a1v.w, o);
    }
    if (lane == 0) {
        float hp = elu1(a0.x * inv) * W2[0] + elu1(a0.y * inv) * W2[1]
                 + elu1(a0.z * inv) * W2[2] + elu1(a0.w * inv) * W2[3]
                 + elu1(a1v.x * inv) * W2[4] + elu1(a1v.y * inv) * W2[5]
                 + elu1(a1v.z * inv) * W2[6] + elu1(a1v.w * inv) * W2[7];
        float e2 = expf(hp * a2[1]);
        g_e2[row] = e2;
        g_q2[row] = e2 * hp;
    }
}

// ------- GAT agg layer 2 (scalar q2 gather) + mask + hop-2/3 flags -----------
__global__ void k_agg2() {
    __shared__ float red[8];
    float inv = 1.0f / block_sum_4096(g_e2, red);

    int row = blockIdx.x * 8 + (threadIdx.x >> 5);
    int lane = threadIdx.x & 31;
    int s = row * DEGMAX, deg = g_deg[row];
    float acc = 0.0f;
    for (int k = lane; k < deg; k += 32) {
        acc += g_q2[g_col[s + k]];
    }
    for (int o = 16; o; o >>= 1) acc += __shfl_xor_sync(~0u, acc, o);
    float mask = 0.0f;
    if (lane == 0) {
        float sc = elu1(acc * inv);
        mask = sc > LAMBDA_ ? 1.0f : 0.0f;
        g_mask[row] = mask;
        if (mask == 0.0f) {
            int slot = atomicAdd(&g_n0, 1);
            g_list[slot] = row;
        }
    }
    mask = __shfl_sync(~0u, mask, 0);
    if (mask == 0.0f) {
        for (int k = lane; k < deg; k += 32) g_need2[g_col[s + k]] = 1;
    }
}

// =================== SpMMs (fp16 gathers, warp-per-row) ======================
// hop1 v-half: y1vh = A@v  (mask-independent)
__global__ void k_spmm1v() {
    int w = threadIdx.x >> 5, lane = threadIdx.x & 31;
    int row = blockIdx.x * 4 + w;
    int s = row * DEGMAX, deg = g_deg[row];
    const uint4* X = (const uint4*)g_z0h;     // 64 uint4 / row; v at +32
    float a[8] = {0, 0, 0, 0, 0, 0, 0, 0};
    int k = 0;
    for (; k + 3 < deg; k += 4) {
        int j0 = g_col[s + k], j1 = g_col[s + k + 1];
        int j2 = g_col[s + k + 2], j3 = g_col[s + k + 3];
        uint4 p0 = X[(size_t)j0 * 64 + 32 + lane];
        uint4 p1 = X[(size_t)j1 * 64 + 32 + lane];
        uint4 p2 = X[(size_t)j2 * 64 + 32 + lane];
        uint4 p3 = X[(size_t)j3 * 64 + 32 + lane];
        acc8(a, p0); acc8(a, p1); acc8(a, p2); acc8(a, p3);
    }
    for (; k < deg; k++)
        acc8(a, X[(size_t)g_col[s + k] * 64 + 32 + lane]);
    uint4 o;
    __half2 hh;
    hh = __floats2half2_rn(a[0], a[1]); o.x = *(uint32_t*)&hh;
    hh = __floats2half2_rn(a[2], a[3]); o.y = *(uint32_t*)&hh;
    hh = __floats2half2_rn(a[4], a[5]); o.z = *(uint32_t*)&hh;
    hh = __floats2half2_rn(a[6], a[7]); o.w = *(uint32_t*)&hh;
    ((uint4*)g_y1vh)[(size_t)row * 32 + lane] = o;
}

// fused: even warps -> out = A@u + b (mask=1 rows); odd warps -> y2h = A@y1vh (need2 rows)
__global__ void k_spmm2u(const float* __restrict__ bsgc, float* __restrict__ out) {
    int w = threadIdx.x >> 5, lane = threadIdx.x & 31;
    int row = blockIdx.x * 2 + (w >> 1);
    int s = row * DEGMAX, deg = g_deg[row];
    float a[8] = {0, 0, 0, 0, 0, 0, 0, 0};
    if ((w & 1) == 0) {              // u-task
        if (g_mask[row] == 0.0f) return;
        const uint4* X = (const uint4*)g_z0h;
        int k = 0;
        for (; k + 3 < deg; k += 4) {
            int j0 = g_col[s + k], j1 = g_col[s + k + 1];
            int j2 = g_col[s + k + 2], j3 = g_col[s + k + 3];
            uint4 p0 = X[(size_t)j0 * 64 + lane];
            uint4 p1 = X[(size_t)j1 * 64 + lane];
            uint4 p2 = X[(size_t)j2 * 64 + lane];
            uint4 p3 = X[(size_t)j3 * 64 + lane];
            acc8(a, p0); acc8(a, p1); acc8(a, p2); acc8(a, p3);
        }
        for (; k < deg; k++)
            acc8(a, X[(size_t)g_col[s + k] * 64 + lane]);
        float4 b0 = ((const float4*)bsgc)[lane * 2];
        float4 b1 = ((const float4*)bsgc)[lane * 2 + 1];
        ((float4*)out)[(size_t)row * 64 + lane * 2] =
            make_float4(a[0] + b0.x, a[1] + b0.y, a[2] + b0.z, a[3] + b0.w);
        ((float4*)out)[(size_t)row * 64 + lane * 2 + 1] =
            make_float4(a[4] + b1.x, a[5] + b1.y, a[6] + b1.z, a[7] + b1.w);
    } else {                          // y2-task
        if (!g_need2[row]) return;
        const uint4* X = (const uint4*)g_y1vh;
        int k = 0;
        for (; k + 3 < deg; k += 4) {
            int j0 = g_col[s + k], j1 = g_col[s + k + 1];
            int j2 = g_col[s + k + 2], j3 = g_col[s + k + 3];
            uint4 p0 = X[(size_t)j0 * 32 + lane];
            uint4 p1 = X[(size_t)j1 * 32 + lane];
            uint4 p2 = X[(size_t)j2 * 32 + lane];
            uint4 p3 = X[(size_t)j3 * 32 + lane];
            acc8(a, p0); acc8(a, p1); acc8(a, p2); acc8(a, p3);
        }
        for (; k < deg; k++)
            acc8(a, X[(size_t)g_col[s + k] * 32 + lane]);
        uint4 o;
        __half2 hh;
        hh = __floats2half2_rn(a[0], a[1]); o.x = *(uint32_t*)&hh;
        hh = __floats2half2_rn(a[2], a[3]); o.y = *(uint32_t*)&hh;
        hh = __floats2half2_rn(a[4], a[5]); o.z = *(uint32_t*)&hh;
        hh = __floats2half2_rn(a[6], a[7]); o.w = *(uint32_t*)&hh;
        ((uint4*)g_y2h)[(size_t)row * 32 + lane] = o;
    }
}

// hop3: out = A@y2 + bias, masked-0 rows (compacted list), warp-per-entry
__global__ void k_spmm3(const float* __restrict__ bsgc, float* __restrict__ out) {
    int w = threadIdx.x >> 5, lane = threadIdx.x & 31;
    int b = blockIdx.x * 4 + w;
    if (b >= g_n0) return;
    int row = g_list[b];
    int s = row * DEGMAX, deg = g_deg[row];
    const uint4* X = (const uint4*)g_y2h;
    float a[8] = {0, 0, 0, 0, 0, 0, 0, 0};
    int k = 0;
    for (; k + 3 < deg; k += 4) {
        int j0 = g_col[s + k], j1 = g_col[s + k + 1];
        int j2 = g_col[s + k + 2], j3 = g_col[s + k + 3];
        uint4 p0 = X[(size_t)j0 * 32 + lane];
        uint4 p1 = X[(size_t)j1 * 32 + lane];
        uint4 p2 = X[(size_t)j2 * 32 + lane];
        uint4 p3 = X[(size_t)j3 * 32 + lane];
        acc8(a, p0); acc8(a, p1); acc8(a, p2); acc8(a, p3);
    }
    for (; k < deg; k++)
        acc8(a, X[(size_t)g_col[s + k] * 32 + lane]);
    float4 b0 = ((const float4*)bsgc)[lane * 2];
    float4 b1 = ((const float4*)bsgc)[lane * 2 + 1];
    ((float4*)out)[(size_t)row * 64 + lane * 2] =
        make_float4(a[0] + b0.x, a[1] + b0.y, a[2] + b0.z, a[3] + b0.w);
    ((float4*)out)[(size_t)row * 64 + lane * 2 + 1] =
        make_float4(a[4] + b1.x, a[5] + b1.y, a[6] + b1.z, a[7] + b1.w);
}

// =================== launch (two-stream fork-join graph) =====================
extern "C" void kernel_launch(void* const* d_in, const int* in_sizes, int n_in,
                              void* d_out, int out_size) {
    const float* x    = (const float*)d_in[0];
    const float* adj  = (const float*)d_in[1];
    const float* W1   = (const float*)d_in[2];
    const float* a1   = (const float*)d_in[3];
    const float* W2   = (const float*)d_in[4];
    const float* a2   = (const float*)d_in[5];
    const float* Wsgc = (const float*)d_in[6];
    const float* bsgc = (const float*)d_in[7];
    float* out = (float*)d_out;

    cudaStream_t s1;
    cudaStreamCreate(&s1);
    cudaEvent_t eStart, eConv, eAgg2;
    cudaEventCreateWithFlags(&eStart, cudaEventDisableTiming);
    cudaEventCreateWithFlags(&eConv,  cudaEventDisableTiming);
    cudaEventCreateWithFlags(&eAgg2,  cudaEventDisableTiming);

    // fork
    cudaEventRecord(eStart, 0);
    cudaStreamWaitEvent(s1, eStart, 0);

    // stream s1: CSR build (parallel with conv)
    k_csr<<<512, 256, 0, s1>>>(adj);

    // stream 0: conversions + fused x@W1 front-end, GEMM (fp16 out), A@v
    k_conv<<<2560, 256>>>(x, Wsgc, W1, a1);
    cudaEventRecord(eConv, 0);
    k_gemm<<<dim3(32, 4), 256>>>();
    k_spmm1v<<<1024, 128>>>();

    // stream s1: GAT chain (needs conv + CSR)
    cudaStreamWaitEvent(s1, eConv, 0);
    k_agg1<<<512, 256, 0, s1>>>(W2, a2);
    k_agg2<<<512, 256, 0, s1>>>();
    cudaEventRecord(eAgg2, s1);

    // join: fused u-output + hop2, then hop3
    cudaStreamWaitEvent(0, eAgg2, 0);
    k_spmm2u<<<2048, 128>>>(bsgc, out);
    k_spmm3<<<1024, 128>>>(bsgc, out);

    cudaEventDestroy(eStart);
    cudaEventDestroy(eConv);
    cudaEventDestroy(eAgg2);
    cudaStreamDestroy(s1);
}